// round 17
// baseline (speedup 1.0000x reference)
#include <cuda_runtime.h>
#include <cuda_bf16.h>

#define HH 2048
#define WW 2048

__device__ constexpr float CM[8][8] = {
  { 1.0f,         1.0f,         1.0f,         1.0f,         1.0f,         1.0f,         1.0f,         1.0f        },
  { 0.98078528f,  0.83146961f,  0.55557023f,  0.19509032f, -0.19509032f, -0.55557023f, -0.83146961f, -0.98078528f },
  { 0.92387953f,  0.38268343f, -0.38268343f, -0.92387953f, -0.92387953f, -0.38268343f,  0.38268343f,  0.92387953f },
  { 0.83146961f, -0.19509032f, -0.98078528f, -0.55557023f,  0.55557023f,  0.98078528f,  0.19509032f, -0.83146961f },
  { 0.70710678f, -0.70710678f, -0.70710678f,  0.70710678f,  0.70710678f, -0.70710678f, -0.70710678f,  0.70710678f },
  { 0.55557023f, -0.98078528f,  0.19509032f,  0.83146961f, -0.83146961f, -0.19509032f,  0.98078528f, -0.55557023f },
  { 0.38268343f, -0.92387953f,  0.92387953f, -0.38268343f, -0.38268343f,  0.92387953f, -0.92387953f,  0.38268343f },
  { 0.19509032f, -0.55557023f,  0.83146961f, -0.98078528f,  0.98078528f, -0.83146961f,  0.55557023f, -0.19509032f },
};

// Full per-tile IDCT for one thread: dequant -> pass1 -> 8-lane shuffle
// transpose (3-stage butterfly, width 8) -> pass2. All in registers.
// On entry: ra/rb = 8 coeffs of row x of block q; da/db4 = dequant scales.
// On exit: p[u] = pixel column v=x of block q, rows u=0..7.
__device__ __forceinline__ void idct_block(
    float4 ra, float4 rb, float4 da, float4 db4, int x, float p[8])
{
    float a0 = ra.x * da.x, a1 = ra.y * da.y, a2 = ra.z * da.z, a3 = ra.w * da.w;
    float a4 = rb.x * db4.x, a5 = rb.y * db4.y, a6 = rb.z * db4.z, a7 = rb.w * db4.w;

    float t[8];
#pragma unroll
    for (int v = 0; v < 8; v++) {
        float acc = a0 * CM[0][v];
        acc = fmaf(a1, CM[1][v], acc);
        acc = fmaf(a2, CM[2][v], acc);
        acc = fmaf(a3, CM[3][v], acc);
        acc = fmaf(a4, CM[4][v], acc);
        acc = fmaf(a5, CM[5][v], acc);
        acc = fmaf(a6, CM[6][v], acc);
        acc = fmaf(a7, CM[7][v], acc);
        t[v] = acc;
    }

    // 8x8 transpose across the aligned 8-lane group: after this,
    // lane l's t[i] = (original lane i's t[l]); thread becomes column v=l.
#pragma unroll
    for (int j = 1; j < 8; j <<= 1) {
        bool up = (x & j) != 0;
#pragma unroll
        for (int i = 0; i < 8; i++) {
            if ((i & j) == 0) {
                int jj = i | j;
                float send = up ? t[i] : t[jj];
                float recv = __shfl_xor_sync(0xFFFFFFFFu, send, j, 8);
                if (up) t[i] = recv; else t[jj] = recv;
            }
        }
    }

#pragma unroll
    for (int u = 0; u < 8; u++) {
        float acc = t[0] * CM[0][u];
        acc = fmaf(t[1], CM[1][u], acc);
        acc = fmaf(t[2], CM[2][u], acc);
        acc = fmaf(t[3], CM[3][u], acc);
        acc = fmaf(t[4], CM[4][u], acc);
        acc = fmaf(t[5], CM[5][u], acc);
        acc = fmaf(t[6], CM[6][u], acc);
        acc = fmaf(t[7], CM[7][u], acc);
        p[u] = acc;
    }
}

// One CTA = TWO adjacent 32x32 RGB tiles, cp.async-pipelined.
// R17: smem transpose (sT) replaced by in-register shuffle transpose —
// removes 16 LDS/STS per thread per tile and one barrier per tile.
__global__ __launch_bounds__(256, 6) void jpeg_decode_kernel(
    const float* __restrict__ ycoef, const float* __restrict__ cbcoef,
    const float* __restrict__ crcoef,
    const float* __restrict__ y_table, const float* __restrict__ c_table,
    const float* __restrict__ alpha, const float* __restrict__ shift,
    const float* __restrict__ matrix, const int* __restrict__ factor_i,
    float* __restrict__ out)
{
    __shared__ float sD[128];
    __shared__ float sM[9];
    __shared__ float sK[3];
    __shared__ float sPY[32 * 32];
    __shared__ float sPCb[16 * 18];
    __shared__ float sPCr[16 * 18];
    __shared__ __align__(16) float bufB[24 * 96]; // tile-B coeff staging

    const int tid = threadIdx.x;
    const unsigned tx = blockIdx.x, ty = blockIdx.y, bz = blockIdx.z;
    const unsigned Wb8 = WW / 8, Wb16 = WW / 16;
    const unsigned nY = (HH / 8) * (WW / 8);
    const unsigned nC = (HH / 16) * (WW / 16);

    int fbits = factor_i[0];
    float fac = (fbits > 0 && fbits < (1 << 23)) ? (float)fbits
                                                 : __int_as_float(fbits);

    const int q = tid >> 3;
    const int x = tid & 7;

    // ---- issue tile-A LDG (regs) and tile-B cp.async (smem) first ----
    float4 ra, rb;
    int dsel = 0;
    if (tid < 192) {
        const float* src;
        unsigned n;
        unsigned tx2 = tx * 2;
        if (q < 16) {
            int i = q >> 2, j = q & 3;
            n = bz * nY + (ty * 4 + i) * Wb8 + (tx2 * 4 + j);
            src = ycoef;
        } else if (q < 20) {
            int i = (q - 16) >> 1, j = q & 1;
            n = bz * nC + (ty * 2 + i) * Wb16 + (tx2 * 2 + j);
            src = cbcoef; dsel = 64;
        } else {
            int i = (q - 20) >> 1, j = q & 1;
            n = bz * nC + (ty * 2 + i) * Wb16 + (tx2 * 2 + j);
            src = crcoef; dsel = 64;
        }
        unsigned nB = n + (q < 16 ? 4u : 2u);
        const float4* gA = (const float4*)(src + (size_t)n * 64 + x * 8);
        const float4* gB = (const float4*)(src + (size_t)nB * 64 + x * 8);

        unsigned w = (unsigned)(q * 96 + 12 * x);
        unsigned sdst = (unsigned)__cvta_generic_to_shared(&bufB[w]);
        asm volatile("cp.async.cg.shared.global [%0], [%1], 16;\n"
                     :: "r"(sdst), "l"(gB) : "memory");
        asm volatile("cp.async.cg.shared.global [%0], [%1], 16;\n"
                     :: "r"(sdst + 16), "l"(gB + 1) : "memory");

        ra = __ldcs(&gA[0]);
        rb = __ldcs(&gA[1]);
    }
    asm volatile("cp.async.commit_group;\n" ::: "memory");

    // ---- stage constants ----
    if (tid < 128) {
        const float* tab = (tid < 64) ? y_table : c_table;
        int o = tid & 63;
        sD[tid] = tab[o] * alpha[o] * fac * 0.25f;
    } else if (tid < 137) {
        sM[tid - 128] = matrix[tid - 128] * (1.0f / 255.0f);
    } else if (tid < 140) {
        int d = tid - 137;
        float k = 0.0f;
#pragma unroll
        for (int c = 0; c < 3; c++)
            k = fmaf(128.0f + shift[c], matrix[c * 3 + d], k);
        sK[d] = k * (1.0f / 255.0f);
    }
    __syncthreads();   // sD/sM/sK ready

    const int db = dsel + x * 8;

    // destination pointer in planar pixel buffer (same for tiles A and B)
    float* pdst; int pstride;
    {
        const int v = x;
        if (q < 16) { pdst = &sPY[((q >> 2) * 8) * 32 + (q & 3) * 8 + v]; pstride = 32; }
        else if (q < 20) { int b = q - 16; pdst = &sPCb[((b >> 1) * 8) * 18 + (b & 1) * 8 + v]; pstride = 18; }
        else { int b = q - 20; pdst = &sPCr[((b >> 1) * 8) * 18 + (b & 1) * 8 + v]; pstride = 18; }
    }

    // ---- tile A: full IDCT in registers, then scatter to sP ----
    if (tid < 192) {
        float4 da = *(const float4*)&sD[db];
        float4 db4 = *(const float4*)&sD[db + 4];
        float p[8];
        idct_block(ra, rb, da, db4, x, p);
#pragma unroll
        for (int u = 0; u < 8; u++) pdst[u * pstride] = p[u];
    }
    __syncthreads();

    const int py = tid >> 3;
    const int px0 = (tid & 7) * 4;
    const int cy = py >> 1, cxb = px0 >> 1;
    const unsigned HW = HH * WW;
    const unsigned base = bz * 3u * HW;
    const unsigned gy = ty * 32 + py;

    // ---- epilogue A ----
    {
        const float M0 = sM[0], M1 = sM[1], M2 = sM[2];
        const float M3 = sM[3], M4 = sM[4], M5 = sM[5];
        const float M6 = sM[6], M7 = sM[7], M8 = sM[8];
        const float K0 = sK[0], K1 = sK[1], K2 = sK[2];

        float2 cbv = *(const float2*)&sPCb[cy * 18 + cxb];
        float2 crv = *(const float2*)&sPCr[cy * 18 + cxb];
        float4 yv = *(const float4*)&sPY[py * 32 + px0];

        float bR0 = fmaf(cbv.x, M3, fmaf(crv.x, M6, K0));
        float bG0 = fmaf(cbv.x, M4, fmaf(crv.x, M7, K1));
        float bB0 = fmaf(cbv.x, M5, fmaf(crv.x, M8, K2));
        float bR1 = fmaf(cbv.y, M3, fmaf(crv.y, M6, K0));
        float bG1 = fmaf(cbv.y, M4, fmaf(crv.y, M7, K1));
        float bB1 = fmaf(cbv.y, M5, fmaf(crv.y, M8, K2));

        float4 oR, oG, oB;
        oR.x = __saturatef(fmaf(yv.x, M0, bR0));
        oG.x = __saturatef(fmaf(yv.x, M1, bG0));
        oB.x = __saturatef(fmaf(yv.x, M2, bB0));
        oR.y = __saturatef(fmaf(yv.y, M0, bR0));
        oG.y = __saturatef(fmaf(yv.y, M1, bG0));
        oB.y = __saturatef(fmaf(yv.y, M2, bB0));
        oR.z = __saturatef(fmaf(yv.z, M0, bR1));
        oG.z = __saturatef(fmaf(yv.z, M1, bG1));
        oB.z = __saturatef(fmaf(yv.z, M2, bB1));
        oR.w = __saturatef(fmaf(yv.w, M0, bR1));
        oG.w = __saturatef(fmaf(yv.w, M1, bG1));
        oB.w = __saturatef(fmaf(yv.w, M2, bB1));

        const unsigned gx = (tx * 2) * 32 + px0;
        const unsigned off = gy * WW + gx;
        __stcs((float4*)(out + base + off), oR);
        __stcs((float4*)(out + base + HW + off), oG);
        __stcs((float4*)(out + base + 2u * HW + off), oB);
    }
    __syncthreads();   // epilogue-A reads done before tile-B overwrites sP

    // ---- tile B: consume cp.async data, full IDCT in regs, scatter to sP ----
    if (tid < 192) {
        asm volatile("cp.async.wait_group 0;\n" ::: "memory");
        const float4* bp = (const float4*)&bufB[q * 96 + 12 * x];
        float4 ra2 = bp[0];
        float4 rb2 = bp[1];
        float4 da = *(const float4*)&sD[db];
        float4 db4 = *(const float4*)&sD[db + 4];
        float p[8];
        idct_block(ra2, rb2, da, db4, x, p);
#pragma unroll
        for (int u = 0; u < 8; u++) pdst[u * pstride] = p[u];
    }
    __syncthreads();

    // ---- epilogue B ----
    {
        const float M0 = sM[0], M1 = sM[1], M2 = sM[2];
        const float M3 = sM[3], M4 = sM[4], M5 = sM[5];
        const float M6 = sM[6], M7 = sM[7], M8 = sM[8];
        const float K0 = sK[0], K1 = sK[1], K2 = sK[2];

        float2 cbv = *(const float2*)&sPCb[cy * 18 + cxb];
        float2 crv = *(const float2*)&sPCr[cy * 18 + cxb];
        float4 yv = *(const float4*)&sPY[py * 32 + px0];

        float bR0 = fmaf(cbv.x, M3, fmaf(crv.x, M6, K0));
        float bG0 = fmaf(cbv.x, M4, fmaf(crv.x, M7, K1));
        float bB0 = fmaf(cbv.x, M5, fmaf(crv.x, M8, K2));
        float bR1 = fmaf(cbv.y, M3, fmaf(crv.y, M6, K0));
        float bG1 = fmaf(cbv.y, M4, fmaf(crv.y, M7, K1));
        float bB1 = fmaf(cbv.y, M5, fmaf(crv.y, M8, K2));

        float4 oR, oG, oB;
        oR.x = __saturatef(fmaf(yv.x, M0, bR0));
        oG.x = __saturatef(fmaf(yv.x, M1, bG0));
        oB.x = __saturatef(fmaf(yv.x, M2, bB0));
        oR.y = __saturatef(fmaf(yv.y, M0, bR0));
        oG.y = __saturatef(fmaf(yv.y, M1, bG0));
        oB.y = __saturatef(fmaf(yv.y, M2, bB0));
        oR.z = __saturatef(fmaf(yv.z, M0, bR1));
        oG.z = __saturatef(fmaf(yv.z, M1, bG1));
        oB.z = __saturatef(fmaf(yv.z, M2, bB1));
        oR.w = __saturatef(fmaf(yv.w, M0, bR1));
        oG.w = __saturatef(fmaf(yv.w, M1, bG1));
        oB.w = __saturatef(fmaf(yv.w, M2, bB1));

        const unsigned gx = (tx * 2 + 1) * 32 + px0;
        const unsigned off = gy * WW + gx;
        __stcs((float4*)(out + base + off), oR);
        __stcs((float4*)(out + base + HW + off), oG);
        __stcs((float4*)(out + base + 2u * HW + off), oB);
    }
}

extern "C" void kernel_launch(void* const* d_in, const int* in_sizes, int n_in,
                              void* d_out, int out_size) {
    const float* y      = (const float*)d_in[0];
    const float* cb     = (const float*)d_in[1];
    const float* cr     = (const float*)d_in[2];
    const float* ytab   = (const float*)d_in[3];
    const float* ctab   = (const float*)d_in[4];
    const float* alpha  = (const float*)d_in[5];
    const float* shift  = (const float*)d_in[7];
    const float* matrix = (const float*)d_in[8];
    const int* factor   = (const int*)d_in[11];

    int B = in_sizes[0] / (2048 * 2048);
    if (B < 1) B = 1;

    dim3 grid(WW / 64, HH / 32, B);
    jpeg_decode_kernel<<<grid, 256>>>(y, cb, cr, ytab, ctab, alpha, shift,
                                      matrix, factor, (float*)d_out);
}